// round 2
// baseline (speedup 1.0000x reference)
#include <cuda_runtime.h>
#include <cuda_bf16.h>
#include <cstdint>

#define N_NODES   100000
#define N_EDGES   1600000
#define IN_FEATS  256
#define OUT_FEATS 128

// Scratch: __device__ globals (allocation inside kernel_launch is forbidden).
__device__ float g_hself[(size_t)N_NODES * OUT_FEATS];   // feat @ W
__device__ float g_hneigh[(size_t)N_NODES * OUT_FEATS];  // scatter-sum target
__device__ float g_deg[N_NODES];                         // in-degree
__device__ int   g_idx_is64;                             // index dtype flag

// ---------------------------------------------------------------------------
// Kernel 0: detect index dtype. If the buffer interpreted as int64 yields
// plausible node indices for every sample, it's int64; otherwise int32
// (two int32 indices packed into one int64 read give values >= 2^32 whenever
// the high word is nonzero, which happens with overwhelming probability
// across 4096 samples of uniform [0, 100000) indices).
// ---------------------------------------------------------------------------
__global__ void detect_idx_kernel(const void* dst_raw, int n_elems) {
    __shared__ int bad;
    if (threadIdx.x == 0) bad = 0;
    __syncthreads();
    const long long* p = (const long long*)dst_raw;
    const int samples = 4096;
    for (int i = threadIdx.x; i < samples; i += blockDim.x) {
        // sample spread across the buffer (element count interpretation for
        // int64 would be n_elems; only touch first n_elems/2 int64 slots so
        // the read is in-bounds under EITHER dtype).
        int idx = (int)(((long long)i * (n_elems / 2 - 1)) / (samples - 1));
        long long v = p[idx];
        if (v < 0 || v >= N_NODES) atomicExch(&bad, 1);
    }
    __syncthreads();
    if (threadIdx.x == 0) g_idx_is64 = bad ? 0 : 1;
}

// ---------------------------------------------------------------------------
// Kernel 1: zero h_neigh and deg
// ---------------------------------------------------------------------------
__global__ void zero_kernel() {
    size_t i = (size_t)blockIdx.x * blockDim.x + threadIdx.x;
    const size_t total4 = (size_t)N_NODES * (OUT_FEATS / 4);   // float4 count
    if (i < total4) {
        reinterpret_cast<float4*>(g_hneigh)[i] = make_float4(0.f, 0.f, 0.f, 0.f);
    }
    if (i < N_NODES) {
        g_deg[i] = 0.f;
    }
}

// ---------------------------------------------------------------------------
// Kernel 2: SGEMM  h_self = feat[100000,256] @ W[256,128]
// 128x128 block tile, K-tile 8, 256 threads, 8x8 register tile per thread.
// ---------------------------------------------------------------------------
#define BM 128
#define BN 128
#define BK 8

__global__ __launch_bounds__(256, 2)
void gemm_kernel(const float* __restrict__ feat, const float* __restrict__ W) {
    __shared__ float As[BK][BM + 4];   // padded: conflict-free transposed stores
    __shared__ float Bs[BK][BN];

    const int tid = threadIdx.x;
    const int m0  = blockIdx.x * BM;

    const int arow  = tid >> 1;          // 0..127
    const int acol4 = (tid & 1) * 4;     // 0 or 4
    const int brow  = tid >> 5;          // 0..7
    const int bcol4 = (tid & 31) * 4;    // 0..124

    const int tx = tid & 15;             // col group (8 cols)
    const int ty = tid >> 4;             // row group (8 rows)

    float c[8][8];
    #pragma unroll
    for (int i = 0; i < 8; i++)
        #pragma unroll
        for (int j = 0; j < 8; j++) c[i][j] = 0.f;

    const int grow = m0 + arow;
    const bool arow_ok = (grow < N_NODES);

    for (int k0 = 0; k0 < IN_FEATS; k0 += BK) {
        float4 av = make_float4(0.f, 0.f, 0.f, 0.f);
        if (arow_ok)
            av = *reinterpret_cast<const float4*>(
                     feat + (size_t)grow * IN_FEATS + k0 + acol4);
        As[acol4 + 0][arow] = av.x;
        As[acol4 + 1][arow] = av.y;
        As[acol4 + 2][arow] = av.z;
        As[acol4 + 3][arow] = av.w;

        *reinterpret_cast<float4*>(&Bs[brow][bcol4]) =
            *reinterpret_cast<const float4*>(W + (size_t)(k0 + brow) * OUT_FEATS + bcol4);

        __syncthreads();

        #pragma unroll
        for (int k = 0; k < BK; k++) {
            float a[8], b[8];
            #pragma unroll
            for (int i = 0; i < 8; i++) a[i] = As[k][ty * 8 + i];
            #pragma unroll
            for (int j = 0; j < 8; j++) b[j] = Bs[k][tx * 8 + j];
            #pragma unroll
            for (int i = 0; i < 8; i++)
                #pragma unroll
                for (int j = 0; j < 8; j++)
                    c[i][j] += a[i] * b[j];
        }
        __syncthreads();
    }

    #pragma unroll
    for (int i = 0; i < 8; i++) {
        const int row = m0 + ty * 8 + i;
        if (row < N_NODES) {
            float* o = g_hself + (size_t)row * OUT_FEATS + tx * 8;
            *reinterpret_cast<float4*>(o + 0) =
                make_float4(c[i][0], c[i][1], c[i][2], c[i][3]);
            *reinterpret_cast<float4*>(o + 4) =
                make_float4(c[i][4], c[i][5], c[i][6], c[i][7]);
        }
    }
}

// ---------------------------------------------------------------------------
// Kernel 3: edge scatter.  One warp per edge.
//   lane L handles float4 #L of the 128-float row (32 lanes x 4 = 128).
//   h_neigh[dst] += h_self[src]  via red.global.add.v4.f32
//   deg[dst] += 1 (lane 0)
// Index dtype resolved at runtime via g_idx_is64.
// ---------------------------------------------------------------------------
__global__ __launch_bounds__(256)
void scatter_kernel(const void* __restrict__ src_raw,
                    const void* __restrict__ dst_raw) {
    const int w = (int)((blockIdx.x * (unsigned)blockDim.x + threadIdx.x) >> 5);
    if (w >= N_EDGES) return;
    const int lane = threadIdx.x & 31;

    int s, d;
    if (g_idx_is64) {
        s = (int)((const long long*)src_raw)[w];
        d = (int)((const long long*)dst_raw)[w];
    } else {
        s = ((const int*)src_raw)[w];
        d = ((const int*)dst_raw)[w];
    }
    if ((unsigned)s >= N_NODES || (unsigned)d >= N_NODES) return;  // safety

    const float4 v = *reinterpret_cast<const float4*>(
        g_hself + (size_t)s * OUT_FEATS + lane * 4);

    float* p = g_hneigh + (size_t)d * OUT_FEATS + lane * 4;
    asm volatile("red.global.add.v4.f32 [%0], {%1, %2, %3, %4};"
                 :: "l"(p), "f"(v.x), "f"(v.y), "f"(v.z), "f"(v.w)
                 : "memory");

    if (lane == 0) atomicAdd(&g_deg[d], 1.0f);
}

// ---------------------------------------------------------------------------
// Kernel 4: finalize  out = relu((h_neigh + h_self) / (deg + 1))
// ---------------------------------------------------------------------------
__global__ void finalize_kernel(float* __restrict__ out) {
    const size_t total4 = (size_t)N_NODES * (OUT_FEATS / 4);
    size_t i = (size_t)blockIdx.x * blockDim.x + threadIdx.x;
    if (i >= total4) return;

    const int node = (int)(i >> 5);   // 32 float4 per node
    const float invd = 1.0f / (g_deg[node] + 1.0f);

    const float4 hn = reinterpret_cast<const float4*>(g_hneigh)[i];
    const float4 hs = reinterpret_cast<const float4*>(g_hself)[i];

    float4 r;
    r.x = fmaxf((hn.x + hs.x) * invd, 0.f);
    r.y = fmaxf((hn.y + hs.y) * invd, 0.f);
    r.z = fmaxf((hn.z + hs.z) * invd, 0.f);
    r.w = fmaxf((hn.w + hs.w) * invd, 0.f);

    reinterpret_cast<float4*>(out)[i] = r;
}

// ---------------------------------------------------------------------------
// kernel_launch
//   inputs (metadata order): feat f32[100000,256], W f32[256,128],
//                            src idx[1600000], dst idx[1600000]
//   output: f32[100000,128]
// ---------------------------------------------------------------------------
extern "C" void kernel_launch(void* const* d_in, const int* in_sizes, int n_in,
                              void* d_out, int out_size) {
    const float* feat = (const float*)d_in[0];
    const float* W    = (const float*)d_in[1];
    const void*  src  = d_in[2];
    const void*  dst  = d_in[3];
    float*       out  = (float*)d_out;

    // 0) detect index dtype (1 block, negligible)
    detect_idx_kernel<<<1, 256>>>(dst, in_sizes[3]);

    // 1) zero scratch
    {
        const int total4 = N_NODES * (OUT_FEATS / 4);       // 3.2M
        const int blocks = (total4 + 255) / 256;
        zero_kernel<<<blocks, 256>>>();
    }
    // 2) h_self = feat @ W
    {
        const int blocks = (N_NODES + BM - 1) / BM;         // 782
        gemm_kernel<<<blocks, 256>>>(feat, W);
    }
    // 3) edge scatter (warp per edge) + degree count
    {
        const long long threads = (long long)N_EDGES * 32;  // 51.2M
        const int blocks = (int)((threads + 255) / 256);    // 200000
        scatter_kernel<<<blocks, 256>>>(src, dst);
    }
    // 4) finalize
    {
        const int total4 = N_NODES * (OUT_FEATS / 4);
        const int blocks = (total4 + 255) / 256;
        finalize_kernel<<<blocks, 256>>>(out);
    }
}

// round 4
// speedup vs baseline: 1.3765x; 1.3765x over previous
#include <cuda_runtime.h>
#include <cuda_bf16.h>
#include <cstdint>

#define N_NODES   100000
#define N_EDGES   1600000
#define IN_FEATS  256
#define OUT_FEATS 128

// ---------------------------------------------------------------------------
// Scratch (__device__ globals; allocation in kernel_launch is forbidden)
// ---------------------------------------------------------------------------
__device__ float g_hself[(size_t)N_NODES * OUT_FEATS];
__device__ float g_hneigh[(size_t)N_NODES * OUT_FEATS];
__device__ float g_deg[N_NODES];
__device__ int   g_idx_is64;

// ---------------------------------------------------------------------------
// Kernel 0: detect index dtype (int32 vs int64) — proven in round 2
// ---------------------------------------------------------------------------
__global__ void detect_idx_kernel(const void* dst_raw, int n_elems) {
    __shared__ int bad;
    if (threadIdx.x == 0) bad = 0;
    __syncthreads();
    const long long* p = (const long long*)dst_raw;
    const int samples = 4096;
    for (int i = threadIdx.x; i < samples; i += blockDim.x) {
        int idx = (int)(((long long)i * (n_elems / 2 - 1)) / (samples - 1));
        long long v = p[idx];
        if (v < 0 || v >= N_NODES) atomicExch(&bad, 1);
    }
    __syncthreads();
    if (threadIdx.x == 0) g_idx_is64 = bad ? 0 : 1;
}

// ---------------------------------------------------------------------------
// Kernel 1: zero h_neigh and deg
// ---------------------------------------------------------------------------
__global__ void zero_kernel() {
    size_t i = (size_t)blockIdx.x * blockDim.x + threadIdx.x;
    const size_t total4 = (size_t)N_NODES * (OUT_FEATS / 4);
    if (i < total4)
        reinterpret_cast<float4*>(g_hneigh)[i] = make_float4(0.f, 0.f, 0.f, 0.f);
    if (i < N_NODES) g_deg[i] = 0.f;
}

// ---------------------------------------------------------------------------
// Kernel 2: tf32 mma.sync GEMM   g_hself = feat @ W
//   CTA tile 128x128, BK=32, 8 warps (4x2), warp tile 32x64.
//   m16n8k8.row.col tf32; both operands rounded with cvt.rna.
//   Smem stride 36 floats: fragment LDS conflict-free.
// ---------------------------------------------------------------------------
#define BK 32
#define SSTR 36

__device__ __forceinline__ float to_tf32(float v) {
    asm("cvt.rna.tf32.f32 %0, %1;" : "=f"(v) : "f"(v));
    return v;
}

__device__ __forceinline__ void mma_tf32(float* d, const uint32_t* a,
                                         uint32_t b0, uint32_t b1) {
    asm volatile(
        "mma.sync.aligned.m16n8k8.row.col.f32.tf32.tf32.f32 "
        "{%0,%1,%2,%3}, {%4,%5,%6,%7}, {%8,%9}, {%0,%1,%2,%3};"
        : "+f"(d[0]), "+f"(d[1]), "+f"(d[2]), "+f"(d[3])
        : "r"(a[0]), "r"(a[1]), "r"(a[2]), "r"(a[3]), "r"(b0), "r"(b1));
}

__global__ __launch_bounds__(256, 2)
void gemm_mma_kernel(const float* __restrict__ feat, const float* __restrict__ W) {
    __shared__ float As[128][SSTR];   // [m][k]
    __shared__ float Bs[128][SSTR];   // [n][k]

    const int tid  = threadIdx.x;
    const int lane = tid & 31;
    const int warp = tid >> 5;
    const int m0   = blockIdx.x * 128;

    const int wm = (warp >> 1) * 32;   // warp row base within tile
    const int wn = (warp & 1) * 64;    // warp col base within tile
    const int g  = lane >> 2;          // group id 0..7
    const int c  = lane & 3;           // thread-in-group 0..3

    // A loader: row = (tid>>3) + 32p, k-quad = (tid&7)*4   (coalesced 128B/warp-row)
    const int arow = tid >> 3;         // 0..31
    const int aq   = (tid & 7) * 4;    // 0,4,...,28
    // B loader: k-row = tid>>3, n-quad = (tid&7)*4 + 32p   (W is [k][n], n contiguous)
    const int bkr  = tid >> 3;         // 0..31
    const int bq   = (tid & 7) * 4;    // 0..28 (stride 32 over p)

    float acc[2][8][4];
    #pragma unroll
    for (int i = 0; i < 2; i++)
        #pragma unroll
        for (int j = 0; j < 8; j++)
            #pragma unroll
            for (int q = 0; q < 4; q++) acc[i][j][q] = 0.f;

    float4 pa[4], pb[4];

    // prefetch tile 0
    {
        #pragma unroll
        for (int p = 0; p < 4; p++) {
            int row = m0 + arow + 32 * p;
            row = row < N_NODES ? row : N_NODES - 1;
            pa[p] = *reinterpret_cast<const float4*>(feat + (size_t)row * IN_FEATS + aq);
            pb[p] = *reinterpret_cast<const float4*>(W + (size_t)bkr * OUT_FEATS + bq + 32 * p);
        }
    }

    for (int kt = 0; kt < IN_FEATS / BK; kt++) {
        // store prefetched tile to smem (tf32-rounded)
        #pragma unroll
        for (int p = 0; p < 4; p++) {
            float* a = &As[arow + 32 * p][aq];
            a[0] = to_tf32(pa[p].x); a[1] = to_tf32(pa[p].y);
            a[2] = to_tf32(pa[p].z); a[3] = to_tf32(pa[p].w);
            Bs[bq + 32 * p + 0][bkr] = to_tf32(pb[p].x);
            Bs[bq + 32 * p + 1][bkr] = to_tf32(pb[p].y);
            Bs[bq + 32 * p + 2][bkr] = to_tf32(pb[p].z);
            Bs[bq + 32 * p + 3][bkr] = to_tf32(pb[p].w);
        }
        __syncthreads();

        // prefetch next tile
        if (kt + 1 < IN_FEATS / BK) {
            const int k0 = (kt + 1) * BK;
            #pragma unroll
            for (int p = 0; p < 4; p++) {
                int row = m0 + arow + 32 * p;
                row = row < N_NODES ? row : N_NODES - 1;
                pa[p] = *reinterpret_cast<const float4*>(
                    feat + (size_t)row * IN_FEATS + k0 + aq);
                pb[p] = *reinterpret_cast<const float4*>(
                    W + (size_t)(k0 + bkr) * OUT_FEATS + bq + 32 * p);
            }
        }

        // compute on current smem tile
        #pragma unroll
        for (int ka = 0; ka < 4; ka++) {
            const int klo = ka * 8 + c;
            const int khi = klo + 4;
            uint32_t a[2][4];
            #pragma unroll
            for (int i = 0; i < 2; i++) {
                const int r = wm + i * 16 + g;
                a[i][0] = __float_as_uint(As[r    ][klo]);
                a[i][1] = __float_as_uint(As[r + 8][klo]);
                a[i][2] = __float_as_uint(As[r    ][khi]);
                a[i][3] = __float_as_uint(As[r + 8][khi]);
            }
            #pragma unroll
            for (int j = 0; j < 8; j++) {
                const int n = wn + j * 8 + g;
                const uint32_t b0 = __float_as_uint(Bs[n][klo]);
                const uint32_t b1 = __float_as_uint(Bs[n][khi]);
                mma_tf32(acc[0][j], a[0], b0, b1);
                mma_tf32(acc[1][j], a[1], b0, b1);
            }
        }
        __syncthreads();
    }

    // epilogue: c0,c1 -> (row, 2c..2c+1), c2,c3 -> (row+8, same cols)
    #pragma unroll
    for (int i = 0; i < 2; i++) {
        #pragma unroll
        for (int j = 0; j < 8; j++) {
            const int row0 = m0 + wm + i * 16 + g;
            const int col  = wn + j * 8 + 2 * c;
            if (row0 < N_NODES)
                *reinterpret_cast<float2*>(g_hself + (size_t)row0 * OUT_FEATS + col) =
                    make_float2(acc[i][j][0], acc[i][j][1]);
            const int row1 = row0 + 8;
            if (row1 < N_NODES)
                *reinterpret_cast<float2*>(g_hself + (size_t)row1 * OUT_FEATS + col) =
                    make_float2(acc[i][j][2], acc[i][j][3]);
        }
    }
}

// ---------------------------------------------------------------------------
// Kernel 3: edge scatter (warp per edge; vector RED) — proven in round 2
// ---------------------------------------------------------------------------
__global__ __launch_bounds__(256)
void scatter_kernel(const void* __restrict__ src_raw,
                    const void* __restrict__ dst_raw) {
    const int w = (int)((blockIdx.x * (unsigned)blockDim.x + threadIdx.x) >> 5);
    if (w >= N_EDGES) return;
    const int lane = threadIdx.x & 31;

    int s, d;
    if (g_idx_is64) {
        s = (int)((const long long*)src_raw)[w];
        d = (int)((const long long*)dst_raw)[w];
    } else {
        s = ((const int*)src_raw)[w];
        d = ((const int*)dst_raw)[w];
    }
    if ((unsigned)s >= N_NODES || (unsigned)d >= N_NODES) return;

    const float4 v = *reinterpret_cast<const float4*>(
        g_hself + (size_t)s * OUT_FEATS + lane * 4);

    float* p = g_hneigh + (size_t)d * OUT_FEATS + lane * 4;
    asm volatile("red.global.add.v4.f32 [%0], {%1, %2, %3, %4};"
                 :: "l"(p), "f"(v.x), "f"(v.y), "f"(v.z), "f"(v.w)
                 : "memory");

    if (lane == 0) atomicAdd(&g_deg[d], 1.0f);
}

// ---------------------------------------------------------------------------
// Kernel 4: finalize  out = relu((h_neigh + h_self) / (deg + 1))
// ---------------------------------------------------------------------------
__global__ void finalize_kernel(float* __restrict__ out) {
    const size_t total4 = (size_t)N_NODES * (OUT_FEATS / 4);
    size_t i = (size_t)blockIdx.x * blockDim.x + threadIdx.x;
    if (i >= total4) return;

    const int node = (int)(i >> 5);
    const float invd = 1.0f / (g_deg[node] + 1.0f);

    const float4 hn = reinterpret_cast<const float4*>(g_hneigh)[i];
    const float4 hs = reinterpret_cast<const float4*>(g_hself)[i];

    float4 r;
    r.x = fmaxf((hn.x + hs.x) * invd, 0.f);
    r.y = fmaxf((hn.y + hs.y) * invd, 0.f);
    r.z = fmaxf((hn.z + hs.z) * invd, 0.f);
    r.w = fmaxf((hn.w + hs.w) * invd, 0.f);

    reinterpret_cast<float4*>(out)[i] = r;
}

// ---------------------------------------------------------------------------
// kernel_launch
// ---------------------------------------------------------------------------
extern "C" void kernel_launch(void* const* d_in, const int* in_sizes, int n_in,
                              void* d_out, int out_size) {
    const float* feat = (const float*)d_in[0];
    const float* W    = (const float*)d_in[1];
    const void*  src  = d_in[2];
    const void*  dst  = d_in[3];
    float*       out  = (float*)d_out;

    // 0) detect index dtype
    detect_idx_kernel<<<1, 256>>>(dst, in_sizes[3]);

    // 1) zero scratch
    {
        const int total4 = N_NODES * (OUT_FEATS / 4);
        zero_kernel<<<(total4 + 255) / 256, 256>>>();
    }
    // 2) tf32 tensor-core GEMM
    {
        const int blocks = (N_NODES + 127) / 128;   // 782
        gemm_mma_kernel<<<blocks, 256>>>(feat, W);
    }
    // 3) edge scatter
    {
        const long long threads = (long long)N_EDGES * 32;
        scatter_kernel<<<(int)((threads + 255) / 256), 256>>>(src, dst);
    }
    // 4) finalize
    {
        const int total4 = N_NODES * (OUT_FEATS / 4);
        finalize_kernel<<<(total4 + 255) / 256, 256>>>(out);
    }
}

// round 5
// speedup vs baseline: 2.6380x; 1.9164x over previous
#include <cuda_runtime.h>
#include <cuda_bf16.h>
#include <cstdint>

#define N_NODES   100000
#define N_EDGES   1600000
#define IN_FEATS  256
#define OUT_FEATS 128
#define NB_SCAN   ((N_NODES + 1023) / 1024)   // 98

// ---------------------------------------------------------------------------
// Scratch (__device__ globals; allocation in kernel_launch is forbidden)
// ---------------------------------------------------------------------------
__device__ float g_hself[(size_t)N_NODES * OUT_FEATS];
__device__ int   g_idx_is64;
__device__ int   g_cnt[N_NODES];      // in-degree (CSR row length)
__device__ int   g_off[N_NODES];      // CSR row offsets
__device__ int   g_cur[N_NODES];      // fill cursors
__device__ int   g_ssrc[N_EDGES];     // src ids sorted by dst
__device__ int   g_bsum[NB_SCAN];     // per-block sums for the scan

// ---------------------------------------------------------------------------
// Kernel 0: detect index dtype (int32 vs int64) — proven in round 2
// ---------------------------------------------------------------------------
__global__ void detect_idx_kernel(const void* dst_raw, int n_elems) {
    __shared__ int bad;
    if (threadIdx.x == 0) bad = 0;
    __syncthreads();
    const long long* p = (const long long*)dst_raw;
    const int samples = 4096;
    for (int i = threadIdx.x; i < samples; i += blockDim.x) {
        int idx = (int)(((long long)i * (n_elems / 2 - 1)) / (samples - 1));
        long long v = p[idx];
        if (v < 0 || v >= N_NODES) atomicExch(&bad, 1);
    }
    __syncthreads();
    if (threadIdx.x == 0) g_idx_is64 = bad ? 0 : 1;
}

// ---------------------------------------------------------------------------
// CSR build step 1: zero counters
// ---------------------------------------------------------------------------
__global__ void zero_cnt_kernel() {
    int i = blockIdx.x * blockDim.x + threadIdx.x;
    if (i < N_NODES) g_cnt[i] = 0;
}

// ---------------------------------------------------------------------------
// CSR build step 2: histogram of dst
// ---------------------------------------------------------------------------
__global__ void hist_kernel(const void* __restrict__ dst_raw) {
    int e = blockIdx.x * blockDim.x + threadIdx.x;
    if (e >= N_EDGES) return;
    int d = g_idx_is64 ? (int)((const long long*)dst_raw)[e]
                       : ((const int*)dst_raw)[e];
    if ((unsigned)d < N_NODES) atomicAdd(&g_cnt[d], 1);
}

// ---------------------------------------------------------------------------
// CSR build step 3a: per-1024-block sums
// ---------------------------------------------------------------------------
__global__ void blocksum_kernel() {
    __shared__ int s[1024];
    const int tid = threadIdx.x;
    const int gid = blockIdx.x * 1024 + tid;
    s[tid] = (gid < N_NODES) ? g_cnt[gid] : 0;
    __syncthreads();
    for (int off = 512; off > 0; off >>= 1) {
        if (tid < off) s[tid] += s[tid + off];
        __syncthreads();
    }
    if (tid == 0) g_bsum[blockIdx.x] = s[0];
}

// ---------------------------------------------------------------------------
// CSR build step 3b: serial exclusive scan of 98 block sums (tiny)
// ---------------------------------------------------------------------------
__global__ void scan_bsum_kernel() {
    if (threadIdx.x == 0) {
        int run = 0;
        for (int i = 0; i < NB_SCAN; i++) {
            int v = g_bsum[i];
            g_bsum[i] = run;
            run += v;
        }
    }
}

// ---------------------------------------------------------------------------
// CSR build step 3c: in-block exclusive scan + block offset -> g_off, g_cur
// ---------------------------------------------------------------------------
__global__ void scan_block_kernel() {
    __shared__ int s[1024];
    const int tid = threadIdx.x;
    const int gid = blockIdx.x * 1024 + tid;
    const int v = (gid < N_NODES) ? g_cnt[gid] : 0;
    s[tid] = v;
    __syncthreads();
    // Hillis-Steele inclusive scan
    #pragma unroll
    for (int off = 1; off < 1024; off <<= 1) {
        int t = (tid >= off) ? s[tid - off] : 0;
        __syncthreads();
        s[tid] += t;
        __syncthreads();
    }
    if (gid < N_NODES) {
        const int excl = s[tid] - v + g_bsum[blockIdx.x];
        g_off[gid] = excl;
        g_cur[gid] = excl;
    }
}

// ---------------------------------------------------------------------------
// CSR build step 4: fill sorted-by-dst src list
// ---------------------------------------------------------------------------
__global__ void fill_kernel(const void* __restrict__ src_raw,
                            const void* __restrict__ dst_raw) {
    int e = blockIdx.x * blockDim.x + threadIdx.x;
    if (e >= N_EDGES) return;
    int s, d;
    if (g_idx_is64) {
        s = (int)((const long long*)src_raw)[e];
        d = (int)((const long long*)dst_raw)[e];
    } else {
        s = ((const int*)src_raw)[e];
        d = ((const int*)dst_raw)[e];
    }
    if ((unsigned)s >= N_NODES || (unsigned)d >= N_NODES) return;
    const int pos = atomicAdd(&g_cur[d], 1);
    g_ssrc[pos] = s;
}

// ---------------------------------------------------------------------------
// Kernel 2: tf32 mma.sync GEMM   g_hself = feat @ W   (round-4 proven)
// ---------------------------------------------------------------------------
#define BK 32
#define SSTR 36

__device__ __forceinline__ float to_tf32(float v) {
    asm("cvt.rna.tf32.f32 %0, %1;" : "=f"(v) : "f"(v));
    return v;
}

__device__ __forceinline__ void mma_tf32(float* d, const uint32_t* a,
                                         uint32_t b0, uint32_t b1) {
    asm volatile(
        "mma.sync.aligned.m16n8k8.row.col.f32.tf32.tf32.f32 "
        "{%0,%1,%2,%3}, {%4,%5,%6,%7}, {%8,%9}, {%0,%1,%2,%3};"
        : "+f"(d[0]), "+f"(d[1]), "+f"(d[2]), "+f"(d[3])
        : "r"(a[0]), "r"(a[1]), "r"(a[2]), "r"(a[3]), "r"(b0), "r"(b1));
}

__global__ __launch_bounds__(256, 2)
void gemm_mma_kernel(const float* __restrict__ feat, const float* __restrict__ W) {
    __shared__ float As[128][SSTR];   // [m][k]
    __shared__ float Bs[128][SSTR];   // [n][k]

    const int tid  = threadIdx.x;
    const int lane = tid & 31;
    const int warp = tid >> 5;
    const int m0   = blockIdx.x * 128;

    const int wm = (warp >> 1) * 32;
    const int wn = (warp & 1) * 64;
    const int g  = lane >> 2;
    const int c  = lane & 3;

    const int arow = tid >> 3;
    const int aq   = (tid & 7) * 4;
    const int bkr  = tid >> 3;
    const int bq   = (tid & 7) * 4;

    float acc[2][8][4];
    #pragma unroll
    for (int i = 0; i < 2; i++)
        #pragma unroll
        for (int j = 0; j < 8; j++)
            #pragma unroll
            for (int q = 0; q < 4; q++) acc[i][j][q] = 0.f;

    float4 pa[4], pb[4];

    #pragma unroll
    for (int p = 0; p < 4; p++) {
        int row = m0 + arow + 32 * p;
        row = row < N_NODES ? row : N_NODES - 1;
        pa[p] = *reinterpret_cast<const float4*>(feat + (size_t)row * IN_FEATS + aq);
        pb[p] = *reinterpret_cast<const float4*>(W + (size_t)bkr * OUT_FEATS + bq + 32 * p);
    }

    for (int kt = 0; kt < IN_FEATS / BK; kt++) {
        #pragma unroll
        for (int p = 0; p < 4; p++) {
            float* a = &As[arow + 32 * p][aq];
            a[0] = to_tf32(pa[p].x); a[1] = to_tf32(pa[p].y);
            a[2] = to_tf32(pa[p].z); a[3] = to_tf32(pa[p].w);
            Bs[bq + 32 * p + 0][bkr] = to_tf32(pb[p].x);
            Bs[bq + 32 * p + 1][bkr] = to_tf32(pb[p].y);
            Bs[bq + 32 * p + 2][bkr] = to_tf32(pb[p].z);
            Bs[bq + 32 * p + 3][bkr] = to_tf32(pb[p].w);
        }
        __syncthreads();

        if (kt + 1 < IN_FEATS / BK) {
            const int k0 = (kt + 1) * BK;
            #pragma unroll
            for (int p = 0; p < 4; p++) {
                int row = m0 + arow + 32 * p;
                row = row < N_NODES ? row : N_NODES - 1;
                pa[p] = *reinterpret_cast<const float4*>(
                    feat + (size_t)row * IN_FEATS + k0 + aq);
                pb[p] = *reinterpret_cast<const float4*>(
                    W + (size_t)(k0 + bkr) * OUT_FEATS + bq + 32 * p);
            }
        }

        #pragma unroll
        for (int ka = 0; ka < 4; ka++) {
            const int klo = ka * 8 + c;
            const int khi = klo + 4;
            uint32_t a[2][4];
            #pragma unroll
            for (int i = 0; i < 2; i++) {
                const int r = wm + i * 16 + g;
                a[i][0] = __float_as_uint(As[r    ][klo]);
                a[i][1] = __float_as_uint(As[r + 8][klo]);
                a[i][2] = __float_as_uint(As[r    ][khi]);
                a[i][3] = __float_as_uint(As[r + 8][khi]);
            }
            #pragma unroll
            for (int j = 0; j < 8; j++) {
                const int n = wn + j * 8 + g;
                const uint32_t b0 = __float_as_uint(Bs[n][klo]);
                const uint32_t b1 = __float_as_uint(Bs[n][khi]);
                mma_tf32(acc[0][j], a[0], b0, b1);
                mma_tf32(acc[1][j], a[1], b0, b1);
            }
        }
        __syncthreads();
    }

    #pragma unroll
    for (int i = 0; i < 2; i++) {
        #pragma unroll
        for (int j = 0; j < 8; j++) {
            const int row0 = m0 + wm + i * 16 + g;
            const int col  = wn + j * 8 + 2 * c;
            if (row0 < N_NODES)
                *reinterpret_cast<float2*>(g_hself + (size_t)row0 * OUT_FEATS + col) =
                    make_float2(acc[i][j][0], acc[i][j][1]);
            const int row1 = row0 + 8;
            if (row1 < N_NODES)
                *reinterpret_cast<float2*>(g_hself + (size_t)row1 * OUT_FEATS + col) =
                    make_float2(acc[i][j][2], acc[i][j][3]);
        }
    }
}

// ---------------------------------------------------------------------------
// Kernel 3: CSR aggregate + finalize (fused).  One warp per dst node.
//   lane L owns float4 #L of the 128-float row.
//   out[n] = relu((sum_{s in nbrs(n)} h_self[s] + h_self[n]) / (deg+1))
// ---------------------------------------------------------------------------
__global__ __launch_bounds__(256)
void aggregate_kernel(float* __restrict__ out) {
    const int n = (int)((blockIdx.x * (unsigned)blockDim.x + threadIdx.x) >> 5);
    if (n >= N_NODES) return;
    const int lane = threadIdx.x & 31;

    const int beg = g_off[n];
    const int cnt = g_cnt[n];
    const int end = beg + cnt;

    float4 acc = make_float4(0.f, 0.f, 0.f, 0.f);

    int i = beg;
    for (; i + 2 <= end; i += 2) {
        const int s0 = __ldg(&g_ssrc[i]);
        const int s1 = __ldg(&g_ssrc[i + 1]);
        const float4 v0 = *reinterpret_cast<const float4*>(
            g_hself + (size_t)s0 * OUT_FEATS + lane * 4);
        const float4 v1 = *reinterpret_cast<const float4*>(
            g_hself + (size_t)s1 * OUT_FEATS + lane * 4);
        acc.x += v0.x + v1.x;
        acc.y += v0.y + v1.y;
        acc.z += v0.z + v1.z;
        acc.w += v0.w + v1.w;
    }
    if (i < end) {
        const int s0 = __ldg(&g_ssrc[i]);
        const float4 v0 = *reinterpret_cast<const float4*>(
            g_hself + (size_t)s0 * OUT_FEATS + lane * 4);
        acc.x += v0.x; acc.y += v0.y; acc.z += v0.z; acc.w += v0.w;
    }

    const float4 hs = *reinterpret_cast<const float4*>(
        g_hself + (size_t)n * OUT_FEATS + lane * 4);
    const float invd = 1.0f / ((float)cnt + 1.0f);

    float4 r;
    r.x = fmaxf((acc.x + hs.x) * invd, 0.f);
    r.y = fmaxf((acc.y + hs.y) * invd, 0.f);
    r.z = fmaxf((acc.z + hs.z) * invd, 0.f);
    r.w = fmaxf((acc.w + hs.w) * invd, 0.f);

    *reinterpret_cast<float4*>(out + (size_t)n * OUT_FEATS + lane * 4) = r;
}

// ---------------------------------------------------------------------------
// kernel_launch
// ---------------------------------------------------------------------------
extern "C" void kernel_launch(void* const* d_in, const int* in_sizes, int n_in,
                              void* d_out, int out_size) {
    const float* feat = (const float*)d_in[0];
    const float* W    = (const float*)d_in[1];
    const void*  src  = d_in[2];
    const void*  dst  = d_in[3];
    float*       out  = (float*)d_out;

    // 0) detect index dtype
    detect_idx_kernel<<<1, 256>>>(dst, in_sizes[3]);

    // 1) GEMM (independent of binning; launched first)
    gemm_mma_kernel<<<(N_NODES + 127) / 128, 256>>>(feat, W);

    // 2) CSR build
    zero_cnt_kernel<<<(N_NODES + 255) / 256, 256>>>();
    hist_kernel<<<(N_EDGES + 255) / 256, 256>>>(dst);
    blocksum_kernel<<<NB_SCAN, 1024>>>();
    scan_bsum_kernel<<<1, 32>>>();
    scan_block_kernel<<<NB_SCAN, 1024>>>();
    fill_kernel<<<(N_EDGES + 255) / 256, 256>>>(src, dst);

    // 3) fused aggregate + mean + relu
    {
        const long long threads = (long long)N_NODES * 32;
        aggregate_kernel<<<(int)((threads + 255) / 256), 256>>>(out);
    }
}